// round 17
// baseline (speedup 1.0000x reference)
#include <cuda_runtime.h>
#include <cstdint>

// Demolition_Conv2d: grouped conv (16 groups of 1->32, 3x3, pad 1) + bias,
// per-(cin,cout) 5-bit quant-dequant (scale=15/9), sum over cin.
//
// R17: R14 main kernel (best: cin-pair planes, vertical 4-px slots, NC=4,
// integer-bit quant accumulation) with two isolated fixes:
//  - cout-group-fastest block map (wave-local L2 reuse of taps; R13 evidence)
//  - fast prepass: per-thread 8-pair row segment, aligned LDG.128 + STG.64

#define CIN   16
#define COUT  32
#define HH    112
#define WW    112
#define NB    8
#define NCP   8      // cin pairs
#define HP    114    // padded height
#define WP    114    // padded width
#define NC    4      // couts per thread
#define NS    4      // vertical pixel slots per thread

typedef unsigned long long f2;

__device__ __align__(16) f2 g_X[NB * NCP * HP * WP];   // ~6.65 MB packed planes

__device__ __forceinline__ f2 pk2(float lo, float hi) {
    f2 r; asm("mov.b64 %0, {%1, %2};" : "=l"(r) : "f"(lo), "f"(hi)); return r;
}
__device__ __forceinline__ void fma2i(f2& acc, f2 a, f2 b) {
    asm("fma.rn.f32x2 %0, %1, %2, %0;" : "+l"(acc) : "l"(a), "l"(b));
}
__device__ __forceinline__ void add2i(f2& acc, f2 b) {
    asm("add.rn.f32x2 %0, %0, %1;" : "+l"(acc) : "l"(b));
}
__device__ __forceinline__ void addbits(unsigned& aLo, unsigned& aHi, f2 t) {
    unsigned lo, hi;
    asm("mov.b64 {%0, %1}, %2;" : "=r"(lo), "=r"(hi) : "l"(t));
    aLo += lo;
    aHi += hi;
}

// ---------------- prepass: padded cin-pair planes, fast path --------------
// One thread = 8 consecutive pair-units of one padded row.
//   t in [0,14): covers wp = 8t+1 .. 8t+8  (sources w = 8t .. 8t+7)
//   t==0 also writes wp 0 = 0; t==13 also writes wp 113 = 0.
// Rows: NB*NCP*HP = 7296; threads = 7296*14 = 102144 = 399 * 256.
__global__ __launch_bounds__(256)
void prepass_kernel(const float* __restrict__ x)
{
    int gid = blockIdx.x * 256 + threadIdx.x;
    int t   = gid % 14;
    int row = gid / 14;              // [0, 7296)
    int hp  = row % HP;
    int bc  = row / HP;              // b*NCP + cp
    int cp  = bc % NCP;
    int b   = bc / NCP;

    int h  = hp - 1;
    bool rv = (h >= 0) && (h < HH);
    int w0 = t * 8;

    const float* r0 = x + (((b * CIN + 2 * cp)     * HH + h) * WW) + w0;
    const float* r1 = x + (((b * CIN + 2 * cp + 1) * HH + h) * WW) + w0;

    float4 a0, a1, b0, b1;
    if (rv) {
        a0 = *reinterpret_cast<const float4*>(r0);
        a1 = *reinterpret_cast<const float4*>(r0 + 4);
        b0 = *reinterpret_cast<const float4*>(r1);
        b1 = *reinterpret_cast<const float4*>(r1 + 4);
    } else {
        a0 = a1 = b0 = b1 = make_float4(0.f, 0.f, 0.f, 0.f);
    }

    f2* dst = g_X + (long)row * WP + w0 + 1;   // wp = w0+1 .. w0+8
    dst[0] = pk2(a0.x, b0.x);
    dst[1] = pk2(a0.y, b0.y);
    dst[2] = pk2(a0.z, b0.z);
    dst[3] = pk2(a0.w, b0.w);
    dst[4] = pk2(a1.x, b1.x);
    dst[5] = pk2(a1.y, b1.y);
    dst[6] = pk2(a1.z, b1.z);
    dst[7] = pk2(a1.w, b1.w);

    if (t == 0)  g_X[(long)row * WP + 0]   = 0ULL;   // left pad
    if (t == 13) g_X[(long)row * WP + 113] = 0ULL;   // right pad
}

// ---------------- main kernel (R14, group-fastest block map) --------------
// 1568 blocks = 196 pixel-blocks x 8 cout groups; grp = blockIdx & 7.
__global__ __launch_bounds__(128, 4)
void demolition_conv2d_kernel(const float* __restrict__ Wt,
                              const float* __restrict__ bias,
                              float* __restrict__ out)
{
    __shared__ __align__(16) f2 sW[NCP * NC * 10];   // 2560 B

    const float SCALEf = 15.0f / 9.0f;
    const float INVf   = 9.0f / 15.0f;
    const float MAGICf = 12582912.0f;        // 1.5 * 2^23
    const unsigned MAGB = 0x4B400000u;
    const unsigned BIAS16 = MAGB * 16u;      // mod 2^32 (wraps cancel)

    int grp = blockIdx.x & 7;            // cout group, fastest
    int pb  = blockIdx.x >> 3;           // pixel block 0..195
    int q   = pb * 128 + threadIdx.x;    // [0, 25088)
    int w    = q % WW;
    int band = (q / WW) % 28;
    int b    = q / (WW * 28);
    int h0   = band * NS;
    int co_base = grp * NC;

    for (int i = threadIdx.x; i < NCP * NC * 10; i += 128) {
        int e  = i / 10;
        int k  = i % 10;
        int cp = e / NC;
        int lc = e % NC;
        int co = co_base + lc;
        float v0, v1;
        if (k < 9) {
            v0 = Wt[((2 * cp)     * COUT + co) * 9 + k];
            v1 = Wt[((2 * cp + 1) * COUT + co) * 9 + k];
        } else {
            v0 = bias[(2 * cp)     * COUT + co];
            v1 = bias[(2 * cp + 1) * COUT + co];
        }
        sW[i] = pk2(v0 * SCALEf, v1 * SCALEf);
    }
    __syncthreads();

    const f2 MAG2 = pk2(MAGICf, MAGICf);

    // Integer bit-accumulators (low lane = cin 2cp, high lane = cin 2cp+1).
    unsigned accL[NC][NS], accH[NC][NS];
#pragma unroll
    for (int c = 0; c < NC; ++c)
#pragma unroll
        for (int s = 0; s < NS; ++s) { accL[c][s] = 0u; accH[c][s] = 0u; }

    // Padded plane pointer for cp=0: rows h0..h0+5 cover outputs h0..h0+3.
    const f2* A = g_X + ((long)b * NCP * HP + h0) * WP + w;
    const long PSTRIDE = (long)HP * WP;

#pragma unroll 1
    for (int cp = 0; cp < NCP; ++cp) {
        // 6 rows x 3 cols of taps (coalesced LDG.64 in w).
        f2 tp[6][3];
#pragma unroll
        for (int r = 0; r < 6; ++r) {
#pragma unroll
            for (int k = 0; k < 3; ++k)
                tp[r][k] = A[r * WP + k];
        }
        A += PSTRIDE;

        const ulonglong2* wb =
            reinterpret_cast<const ulonglong2*>(&sW[cp * NC * 10]);

#pragma unroll
        for (int c = 0; c < NC; ++c) {
            ulonglong2 w01 = wb[c * 5 + 0];   // w0, w1
            ulonglong2 w23 = wb[c * 5 + 1];   // w2, w3
            ulonglong2 w45 = wb[c * 5 + 2];   // w4, w5
            ulonglong2 w67 = wb[c * 5 + 3];   // w6, w7
            ulonglong2 w8b = wb[c * 5 + 4];   // w8, bias

#pragma unroll
            for (int s = 0; s < NS; ++s) {
                f2 y = w8b.y;
                fma2i(y, tp[s][0],     w01.x);
                fma2i(y, tp[s][1],     w01.y);
                fma2i(y, tp[s][2],     w23.x);
                fma2i(y, tp[s + 1][0], w23.y);
                fma2i(y, tp[s + 1][1], w45.x);
                fma2i(y, tp[s + 1][2], w45.y);
                fma2i(y, tp[s + 2][0], w67.x);
                fma2i(y, tp[s + 2][1], w67.y);
                fma2i(y, tp[s + 2][2], w8b.x);

                add2i(y, MAG2);                    // RNE: bits = MAGB + q
                addbits(accL[c][s], accH[c][s], y); // alu-pipe accumulation
            }
        }
    }

    // Final: strip 16 magic biases, convert, scale. Coalesced in w.
#pragma unroll
    for (int c = 0; c < NC; ++c) {
        int co = co_base + c;
        float* ob = out + ((long)(b * COUT + co) * HH + h0) * WW + w;
#pragma unroll
        for (int s = 0; s < NS; ++s) {
            int qsum = (int)(accL[c][s] + accH[c][s] - BIAS16);
            ob[s * WW] = (float)qsum * INVf;
        }
    }
}

extern "C" void kernel_launch(void* const* d_in, const int* in_sizes, int n_in,
                              void* d_out, int out_size)
{
    const float* x    = (const float*)d_in[0];   // [8,16,112,112]
    const float* Wt   = (const float*)d_in[1];   // [16,32,1,3,3]
    const float* bias = (const float*)d_in[2];   // [16,32]
    float* out        = (float*)d_out;           // [8,32,112,112]

    // 7296 rows x 14 threads = 102144 = 399 * 256 exactly.
    prepass_kernel<<<399, 256>>>(x);
    // 1568 blocks = 196 pixel-blocks x 8 cout groups (group fastest).
    demolition_conv2d_kernel<<<1568, 128>>>(Wt, bias, out);
}